// round 2
// baseline (speedup 1.0000x reference)
#include <cuda_runtime.h>
#include <cuda_bf16.h>
#include <math.h>

// Problem constants
#define HH 16
#define DHH 64
static constexpr int Bc   = 2;
static constexpr int Nq   = 1024;
static constexpr int NCTX = 2048;
static constexpr int DIM  = 1024;
static constexpr int NMEM = 16;
static constexpr int JJ   = NCTX + NMEM;   // 2064

// ---------------- scratch (device globals; reused across the two layers) ----
static constexpr size_t QN_ELEMS   = (size_t)Bc * HH * Nq * DHH;    // 2,097,152
static constexpr size_t KN_ELEMS   = (size_t)Bc * HH * JJ * DHH;    // 4,227,072
static constexpr size_t DOTS_ELEMS = (size_t)Bc * HH * Nq * (size_t)JJ; // 67,633,152
static constexpr size_t CAT_ELEMS  = (size_t)Bc * Nq * HH * DHH;    // 2,097,152

__device__ float g_qn[QN_ELEMS];
__device__ float g_kn[KN_ELEMS];
__device__ float g_vv[KN_ELEMS];
__device__ float g_dots[DOTS_ELEMS];
__device__ float g_cat[CAT_ELEMS];
__device__ float g_scale[HH];

// ---------------- tiny helper kernels --------------------------------------

__global__ void scale_kernel(float* __restrict__ out, const float* __restrict__ p) {
    int h = threadIdx.x;
    if (h < HH) out[h] = 1.0f / fmaxf(expf(p[h]), 0.01f);
}

// copy mem_k/mem_v [H,NMEM,DH] into the first NMEM rows of kn/vv for each b
__global__ void memfill_kernel(float* __restrict__ kn, float* __restrict__ vv,
                               const float* __restrict__ mk, const float* __restrict__ mv) {
    int idx = blockIdx.x * blockDim.x + threadIdx.x;
    const int total = HH * NMEM * DHH;   // 16384
    if (idx >= total) return;
    int h   = idx / (NMEM * DHH);
    int rem = idx % (NMEM * DHH);
    int m = rem / DHH, d = rem % DHH;
    float k = mk[idx], v = mv[idx];
    for (int b = 0; b < Bc; b++) {
        size_t o = (((size_t)(b * HH + h) * JJ) + m) * DHH + d;
        kn[o] = k; vv[o] = v;
    }
}

// l2-normalize rows of length 64; one warp per row
__global__ void l2norm_kernel(float* __restrict__ buf, int rows) {
    int row = blockIdx.x * 8 + (threadIdx.x >> 5);
    if (row >= rows) return;
    int lane = threadIdx.x & 31;
    float2* p = reinterpret_cast<float2*>(buf + (size_t)row * DHH);
    float2 v = p[lane];
    float ss = v.x * v.x + v.y * v.y;
    #pragma unroll
    for (int o = 16; o; o >>= 1) ss += __shfl_xor_sync(0xffffffffu, ss, o);
    float inv = 1.0f / fmaxf(sqrtf(ss), 1e-12f);
    v.x *= inv; v.y *= inv;
    p[lane] = v;
}

// ---------------- fused talking-heads pre-mix + softmax + post-mix ---------
// one block per (b, i) query row; dots layout [b][h][n][j]; overwritten in place
// dyn smem: 16 * 2064 floats = 132096 B
__global__ void mix_softmax_kernel(float* __restrict__ dots,
                                   const float* __restrict__ th_pre,
                                   const float* __restrict__ th_post) {
    extern __shared__ float sh[];                 // [16][JJ]
    __shared__ float s_pre[HH * HH], s_post[HH * HH];
    __shared__ float red[HH][8];
    __shared__ float gmax[HH], gsum[HH], Mmat[HH * HH];

    const int bi = blockIdx.x;
    const int b = bi / Nq, i = bi % Nq;
    const int tid = threadIdx.x;                  // blockDim = 256
    const int warp = tid >> 5, lane = tid & 31;

    s_pre[tid]  = th_pre[tid];
    s_post[tid] = th_post[tid];

    // load dots for all 16 heads of this row
    for (int h = 0; h < HH; h++) {
        const float* src = dots + (((size_t)(b * HH + h) * Nq + i) * JJ);
        for (int j = tid; j < JJ; j += 256) sh[h * JJ + j] = src[j];
    }
    __syncthreads();

    // pre-mix (in place per owned column j) + local max per mixed head g
    float lmax[HH];
    #pragma unroll
    for (int g = 0; g < HH; g++) lmax[g] = -1e30f;
    for (int j = tid; j < JJ; j += 256) {
        float d[HH];
        #pragma unroll
        for (int h = 0; h < HH; h++) d[h] = sh[h * JJ + j];
        #pragma unroll
        for (int g = 0; g < HH; g++) {
            float m = 0.0f;
            #pragma unroll
            for (int h = 0; h < HH; h++) m = fmaf(s_pre[g * HH + h], d[h], m);
            sh[g * JJ + j] = m;
            lmax[g] = fmaxf(lmax[g], m);
        }
    }
    __syncthreads();
    // block reduce max
    #pragma unroll
    for (int g = 0; g < HH; g++) {
        float v = lmax[g];
        #pragma unroll
        for (int o = 16; o; o >>= 1) v = fmaxf(v, __shfl_xor_sync(0xffffffffu, v, o));
        if (lane == 0) red[g][warp] = v;
    }
    __syncthreads();
    if (tid < HH) {
        float v = red[tid][0];
        #pragma unroll
        for (int w = 1; w < 8; w++) v = fmaxf(v, red[tid][w]);
        gmax[tid] = v;
    }
    __syncthreads();

    // exponentiate + local sums
    float lsum[HH];
    #pragma unroll
    for (int g = 0; g < HH; g++) lsum[g] = 0.0f;
    for (int j = tid; j < JJ; j += 256) {
        #pragma unroll
        for (int g = 0; g < HH; g++) {
            float e = __expf(sh[g * JJ + j] - gmax[g]);
            sh[g * JJ + j] = e;
            lsum[g] += e;
        }
    }
    __syncthreads();
    #pragma unroll
    for (int g = 0; g < HH; g++) {
        float v = lsum[g];
        #pragma unroll
        for (int o = 16; o; o >>= 1) v += __shfl_xor_sync(0xffffffffu, v, o);
        if (lane == 0) red[g][warp] = v;
    }
    __syncthreads();
    if (tid < HH) {
        float v = 0.0f;
        #pragma unroll
        for (int w = 0; w < 8; w++) v += red[tid][w];
        gsum[tid] = v;
    }
    __syncthreads();
    // fold 1/sum into the post-mix matrix: M[g][h] = th_post[g][h]/sum[h]
    Mmat[tid] = s_post[tid] / gsum[tid & 15];
    __syncthreads();

    // post-mix and write back
    for (int j = tid; j < JJ; j += 256) {
        float e[HH];
        #pragma unroll
        for (int h = 0; h < HH; h++) e[h] = sh[h * JJ + j];
        #pragma unroll
        for (int g = 0; g < HH; g++) {
            float o = 0.0f;
            #pragma unroll
            for (int h = 0; h < HH; h++) o = fmaf(Mmat[g * HH + h], e[h], o);
            dots[(((size_t)(b * HH + g) * Nq + i) * JJ) + j] = o;
        }
    }
}

// ---------------- tiled fp32 GEMM with fused epilogues ---------------------
// TRANSB=false: C = A[MxK] * B[KxN]; TRANSB=true: C = A[MxK] * B[NxK]^T
// mode 0: plain, ldc=p1, beta accumulate
// mode 1: split-heads write: p1=rowsPerB, p2=ldRow, p3=rowOff
//         out[((b*16+h)*p2 + p3 + rr)*64 + d]
// mode 2: cat write (batched z=b*16+h): out[((b*p1 + r)*16 + h)*64 + c]
// mode 3: batched plain: out[z*sC + r*p1 + c]
template<int BM, int BN, int BK, int TM, int TN, bool TRANSB>
__global__ void sgemm_kernel(
    int M, int Nc, int K,
    const float* __restrict__ A, int lda, long sA,
    const float* __restrict__ B, int ldb, long sB,
    float* __restrict__ Cout, long sC,
    const float* __restrict__ alphaVec,
    float beta, int mode, int p1, int p2, int p3)
{
    constexpr int NTH = (BM / TM) * (BN / TN);
    __shared__ float As[BK][BM];
    __shared__ float Bs[BK][BN];

    const int z = blockIdx.z;
    const float* Ab = A + (long)z * sA;
    const float* Bb = B + (long)z * sB;
    const int tid = threadIdx.x;
    const int trow = tid / (BN / TN);
    const int tcol = tid % (BN / TN);
    const int rowBase = blockIdx.y * BM;
    const int colBase = blockIdx.x * BN;

    float acc[TM][TN];
    #pragma unroll
    for (int i = 0; i < TM; i++)
        #pragma unroll
        for (int j = 0; j < TN; j++) acc[i][j] = 0.0f;

    for (int k0 = 0; k0 < K; k0 += BK) {
        // A tile (store transposed: As[k][row])
        #pragma unroll
        for (int idx = tid; idx < BM * BK / 4; idx += NTH) {
            int r  = idx / (BK / 4);
            int k4 = (idx % (BK / 4)) * 4;
            int gr = rowBase + r;
            float4 v = make_float4(0.f, 0.f, 0.f, 0.f);
            if (gr < M) v = *reinterpret_cast<const float4*>(&Ab[(long)gr * lda + k0 + k4]);
            As[k4 + 0][r] = v.x; As[k4 + 1][r] = v.y;
            As[k4 + 2][r] = v.z; As[k4 + 3][r] = v.w;
        }
        // B tile
        if (!TRANSB) {
            #pragma unroll
            for (int idx = tid; idx < BK * BN / 4; idx += NTH) {
                int r  = idx / (BN / 4);
                int c4 = (idx % (BN / 4)) * 4;
                int gc = colBase + c4;
                float4 v = make_float4(0.f, 0.f, 0.f, 0.f);
                if (gc < Nc) v = *reinterpret_cast<const float4*>(&Bb[(long)(k0 + r) * ldb + gc]);
                *reinterpret_cast<float4*>(&Bs[r][c4]) = v;
            }
        } else {
            #pragma unroll
            for (int idx = tid; idx < BN * BK / 4; idx += NTH) {
                int c  = idx / (BK / 4);
                int k4 = (idx % (BK / 4)) * 4;
                int gc = colBase + c;
                float4 v = make_float4(0.f, 0.f, 0.f, 0.f);
                if (gc < Nc) v = *reinterpret_cast<const float4*>(&Bb[(long)gc * ldb + k0 + k4]);
                Bs[k4 + 0][c] = v.x; Bs[k4 + 1][c] = v.y;
                Bs[k4 + 2][c] = v.z; Bs[k4 + 3][c] = v.w;
            }
        }
        __syncthreads();

        #pragma unroll
        for (int kk = 0; kk < BK; kk++) {
            float ra[TM], rb[TN];
            #pragma unroll
            for (int i = 0; i < TM; i += 4) {
                float4 v = *reinterpret_cast<const float4*>(&As[kk][trow * TM + i]);
                ra[i] = v.x; ra[i + 1] = v.y; ra[i + 2] = v.z; ra[i + 3] = v.w;
            }
            #pragma unroll
            for (int j = 0; j < TN; j += 4) {
                float4 v = *reinterpret_cast<const float4*>(&Bs[kk][tcol * TN + j]);
                rb[j] = v.x; rb[j + 1] = v.y; rb[j + 2] = v.z; rb[j + 3] = v.w;
            }
            #pragma unroll
            for (int i = 0; i < TM; i++)
                #pragma unroll
                for (int j = 0; j < TN; j++)
                    acc[i][j] = fmaf(ra[i], rb[j], acc[i][j]);
        }
        __syncthreads();
    }

    float alpha = 1.0f;
    if (alphaVec) alpha = alphaVec[z % HH];

    #pragma unroll
    for (int i = 0; i < TM; i++) {
        int gr = rowBase + trow * TM + i;
        if (gr >= M) continue;
        #pragma unroll
        for (int j = 0; j < TN; j++) {
            int gc = colBase + tcol * TN + j;
            if (gc >= Nc) continue;
            float val = alpha * acc[i][j];
            if (mode == 0) {
                float* cp = Cout + (long)gr * p1 + gc;
                *cp = (beta == 0.0f) ? val : fmaf(beta, *cp, val);
            } else if (mode == 1) {
                int b = gr / p1;
                int rr = gr - b * p1;
                int h = gc >> 6, d = gc & 63;
                Cout[(((long)(b * HH + h) * p2 + p3 + rr) << 6) + d] = val;
            } else if (mode == 2) {
                int b = z >> 4, h = z & 15;
                Cout[(((long)(b * p1 + gr) * HH + h) << 6) + gc] = val;
            } else {
                Cout[(long)z * sC + (long)gr * p1 + gc] = val;
            }
        }
    }
}

// ---------------- host launch ----------------------------------------------

static constexpr size_t MIX_SMEM = (size_t)HH * JJ * sizeof(float); // 132096

extern "C" void kernel_launch(void* const* d_in, const int* in_sizes, int n_in,
                              void* d_out, int out_size)
{
    (void)in_sizes; (void)n_in; (void)out_size;
    const float* x   = (const float*)d_in[0];
    const float* ctx = (const float*)d_in[1];
    const float* wq[2]     = {(const float*)d_in[2],  (const float*)d_in[5]};
    const float* wk[2]     = {(const float*)d_in[3],  (const float*)d_in[6]};
    const float* wv[2]     = {(const float*)d_in[4],  (const float*)d_in[7]};
    const float* thpre[2]  = {(const float*)d_in[8],  (const float*)d_in[10]};
    const float* thpost[2] = {(const float*)d_in[9],  (const float*)d_in[11]};
    const float* scp[2]    = {(const float*)d_in[12], (const float*)d_in[13]};
    const float* mk[2]     = {(const float*)d_in[14], (const float*)d_in[16]};
    const float* mv[2]     = {(const float*)d_in[15], (const float*)d_in[17]};
    const float* hs[2]     = {(const float*)d_in[18], (const float*)d_in[19]};
    const float* wo[2]     = {(const float*)d_in[20], (const float*)d_in[21]};
    float* out = (float*)d_out;

    float *qn, *kn, *vv, *dots, *cat, *scl;
    cudaGetSymbolAddress((void**)&qn,   g_qn);
    cudaGetSymbolAddress((void**)&kn,   g_kn);
    cudaGetSymbolAddress((void**)&vv,   g_vv);
    cudaGetSymbolAddress((void**)&dots, g_dots);
    cudaGetSymbolAddress((void**)&cat,  g_cat);
    cudaGetSymbolAddress((void**)&scl,  g_scale);

    cudaFuncSetAttribute(mix_softmax_kernel,
                         cudaFuncAttributeMaxDynamicSharedMemorySize, (int)MIX_SMEM);

    for (int l = 0; l < 2; l++) {
        scale_kernel<<<1, 16>>>(scl, scp[l]);

        // Q = x @ wq  -> qn [b][h][n][d]
        sgemm_kernel<128, 128, 16, 8, 8, false><<<dim3(8, 16, 1), 256>>>(
            Bc * Nq, DIM, DIM, x, DIM, 0, wq[l], DIM, 0, qn, 0,
            nullptr, 0.0f, 1, Nq, Nq, 0);

        const float* c = ctx + (size_t)l * Bc * NCTX * DIM;
        // K = ctx @ wk -> kn rows [NMEM..J)
        sgemm_kernel<128, 128, 16, 8, 8, false><<<dim3(8, 32, 1), 256>>>(
            Bc * NCTX, DIM, DIM, c, DIM, 0, wk[l], DIM, 0, kn, 0,
            nullptr, 0.0f, 1, NCTX, JJ, NMEM);
        // V = ctx @ wv -> vv rows [NMEM..J)
        sgemm_kernel<128, 128, 16, 8, 8, false><<<dim3(8, 32, 1), 256>>>(
            Bc * NCTX, DIM, DIM, c, DIM, 0, wv[l], DIM, 0, vv, 0,
            nullptr, 0.0f, 1, NCTX, JJ, NMEM);

        memfill_kernel<<<64, 256>>>(kn, vv, mk[l], mv[l]);

        l2norm_kernel<<<(Bc * HH * Nq + 7) / 8, 256>>>(qn, Bc * HH * Nq);
        l2norm_kernel<<<(Bc * HH * JJ + 7) / 8, 256>>>(kn, Bc * HH * JJ);

        // dots = scale[h] * qn @ kn^T   (batched over z = b*16+h)
        sgemm_kernel<128, 128, 16, 8, 8, true><<<dim3(17, 8, 32), 256>>>(
            Nq, JJ, DHH, qn, DHH, (long)Nq * DHH, kn, DHH, (long)JJ * DHH,
            dots, (long)Nq * JJ, scl, 0.0f, 3, JJ, 0, 0);

        // talking-heads pre-mix + softmax + post-mix (in place)
        mix_softmax_kernel<<<Bc * Nq, 256, MIX_SMEM>>>(dots, thpre[l], thpost[l]);

        // out_heads = hs[h] * attn @ v -> cat [b][n][h][d]
        sgemm_kernel<128, 64, 16, 8, 8, false><<<dim3(1, 8, 32), 128>>>(
            Nq, DHH, JJ, dots, JJ, (long)Nq * JJ, vv, DHH, (long)JJ * DHH,
            cat, 0, hs[l], 0.0f, 2, Nq, 0, 0);

        // out (+)= cat @ wo
        sgemm_kernel<128, 128, 16, 8, 8, false><<<dim3(8, 16, 1), 256>>>(
            Bc * Nq, DIM, DIM, cat, DIM, 0, wo[l], DIM, 0, out, 0,
            nullptr, (l == 0 ? 0.0f : 1.0f), 0, DIM, 0, 0);
    }
}

// round 5
// speedup vs baseline: 1.2972x; 1.2972x over previous
#include <cuda_runtime.h>
#include <cuda_bf16.h>
#include <math.h>
#include <stdint.h>

// Problem constants
#define HH 16
#define DHH 64
static constexpr int Bc   = 2;
static constexpr int Nq   = 1024;
static constexpr int NCTX = 2048;
static constexpr int DIM  = 1024;
static constexpr int NMEM = 16;
static constexpr int JJ   = NCTX + NMEM;   // 2064

// ---------------- scratch (device globals) ----------------------------------
static constexpr size_t QN_ELEMS   = (size_t)Bc * HH * Nq * DHH;
static constexpr size_t KN_ELEMS   = (size_t)Bc * HH * JJ * DHH;
static constexpr size_t DOTS_ELEMS = (size_t)Bc * HH * Nq * (size_t)JJ;
static constexpr size_t CAT_ELEMS  = (size_t)Bc * Nq * HH * DHH;

__device__ float g_qn[QN_ELEMS];
__device__ float g_kn[KN_ELEMS];
__device__ float g_vv[KN_ELEMS];
__device__ float g_dots[DOTS_ELEMS];
__device__ float g_cat[CAT_ELEMS];
__device__ float g_scale[HH];

// ---------------- tiny helper kernels ---------------------------------------

__global__ void scale_kernel(float* __restrict__ out, const float* __restrict__ p) {
    int h = threadIdx.x;
    if (h < HH) out[h] = 1.0f / fmaxf(expf(p[h]), 0.01f);
}

__global__ void memfill_kernel(float* __restrict__ kn, float* __restrict__ vv,
                               const float* __restrict__ mk, const float* __restrict__ mv) {
    int idx = blockIdx.x * blockDim.x + threadIdx.x;
    const int total = HH * NMEM * DHH;
    if (idx >= total) return;
    int h   = idx / (NMEM * DHH);
    int rem = idx % (NMEM * DHH);
    int m = rem / DHH, d = rem % DHH;
    float k = mk[idx], v = mv[idx];
    for (int b = 0; b < Bc; b++) {
        size_t o = (((size_t)(b * HH + h) * JJ) + m) * DHH + d;
        kn[o] = k; vv[o] = v;
    }
}

__global__ void l2norm_kernel(float* __restrict__ buf, int rows) {
    int row = blockIdx.x * 8 + (threadIdx.x >> 5);
    if (row >= rows) return;
    int lane = threadIdx.x & 31;
    float2* p = reinterpret_cast<float2*>(buf + (size_t)row * DHH);
    float2 v = p[lane];
    float ss = v.x * v.x + v.y * v.y;
    #pragma unroll
    for (int o = 16; o; o >>= 1) ss += __shfl_xor_sync(0xffffffffu, ss, o);
    float inv = 1.0f / fmaxf(sqrtf(ss), 1e-12f);
    v.x *= inv; v.y *= inv;
    p[lane] = v;
}

// ---------------- fused talking-heads pre-mix + softmax + post-mix ----------
__global__ void mix_softmax_kernel(float* __restrict__ dots,
                                   const float* __restrict__ th_pre,
                                   const float* __restrict__ th_post) {
    extern __shared__ float sh[];                 // [16][JJ]
    __shared__ float s_pre[HH * HH], s_post[HH * HH];
    __shared__ float red[HH][8];
    __shared__ float gmax[HH], gsum[HH], Mmat[HH * HH];

    const int bi = blockIdx.x;
    const int b = bi / Nq, i = bi % Nq;
    const int tid = threadIdx.x;
    const int warp = tid >> 5, lane = tid & 31;

    s_pre[tid]  = th_pre[tid];
    s_post[tid] = th_post[tid];

    for (int h = 0; h < HH; h++) {
        const float* src = dots + (((size_t)(b * HH + h) * Nq + i) * JJ);
        for (int j = tid; j < JJ; j += 256) sh[h * JJ + j] = src[j];
    }
    __syncthreads();

    float lmax[HH];
    #pragma unroll
    for (int g = 0; g < HH; g++) lmax[g] = -1e30f;
    for (int j = tid; j < JJ; j += 256) {
        float d[HH];
        #pragma unroll
        for (int h = 0; h < HH; h++) d[h] = sh[h * JJ + j];
        #pragma unroll
        for (int g = 0; g < HH; g++) {
            float m = 0.0f;
            #pragma unroll
            for (int h = 0; h < HH; h++) m = fmaf(s_pre[g * HH + h], d[h], m);
            sh[g * JJ + j] = m;
            lmax[g] = fmaxf(lmax[g], m);
        }
    }
    __syncthreads();
    #pragma unroll
    for (int g = 0; g < HH; g++) {
        float v = lmax[g];
        #pragma unroll
        for (int o = 16; o; o >>= 1) v = fmaxf(v, __shfl_xor_sync(0xffffffffu, v, o));
        if (lane == 0) red[g][warp] = v;
    }
    __syncthreads();
    if (tid < HH) {
        float v = red[tid][0];
        #pragma unroll
        for (int w = 1; w < 8; w++) v = fmaxf(v, red[tid][w]);
        gmax[tid] = v;
    }
    __syncthreads();

    float lsum[HH];
    #pragma unroll
    for (int g = 0; g < HH; g++) lsum[g] = 0.0f;
    for (int j = tid; j < JJ; j += 256) {
        #pragma unroll
        for (int g = 0; g < HH; g++) {
            float e = __expf(sh[g * JJ + j] - gmax[g]);
            sh[g * JJ + j] = e;
            lsum[g] += e;
        }
    }
    __syncthreads();
    #pragma unroll
    for (int g = 0; g < HH; g++) {
        float v = lsum[g];
        #pragma unroll
        for (int o = 16; o; o >>= 1) v += __shfl_xor_sync(0xffffffffu, v, o);
        if (lane == 0) red[g][warp] = v;
    }
    __syncthreads();
    if (tid < HH) {
        float v = 0.0f;
        #pragma unroll
        for (int w = 0; w < 8; w++) v += red[tid][w];
        gsum[tid] = v;
    }
    __syncthreads();
    Mmat[tid] = s_post[tid] / gsum[tid & 15];
    __syncthreads();

    for (int j = tid; j < JJ; j += 256) {
        float e[HH];
        #pragma unroll
        for (int h = 0; h < HH; h++) e[h] = sh[h * JJ + j];
        #pragma unroll
        for (int g = 0; g < HH; g++) {
            float o = 0.0f;
            #pragma unroll
            for (int h = 0; h < HH; h++) o = fmaf(Mmat[g * HH + h], e[h], o);
            dots[(((size_t)(b * HH + g) * Nq + i) * JJ) + j] = o;
        }
    }
}

// ---------------- tf32x3 tensor-core GEMM (fp32-accurate) --------------------
// Each fp32 operand is split hi/lo (3xTF32 scheme):
//   hi = tf32(x), lo = tf32(x - hi);  a*b ~= a_lo*b_hi + a_hi*b_lo + a_hi*b_hi
// Dropped lo*lo term is ~2^-22 relative -> effectively fp32 accuracy.

__device__ __forceinline__ uint32_t f2tf32(float f) {
    uint32_t r;
    asm("cvt.rna.tf32.f32 %0, %1;" : "=r"(r) : "f"(f));
    return r;
}
__device__ __forceinline__ void split_tf32(float f, uint32_t& hi, uint32_t& lo) {
    hi = f2tf32(f);
    lo = f2tf32(f - __uint_as_float(hi));
}

__device__ __forceinline__ void mma_tf32(float* c, const uint32_t* a, const uint32_t* b) {
    asm volatile(
        "mma.sync.aligned.m16n8k8.row.col.f32.tf32.tf32.f32 "
        "{%0,%1,%2,%3}, {%4,%5,%6,%7}, {%8,%9}, {%0,%1,%2,%3};"
        : "+f"(c[0]), "+f"(c[1]), "+f"(c[2]), "+f"(c[3])
        : "r"(a[0]), "r"(a[1]), "r"(a[2]), "r"(a[3]),
          "r"(b[0]), "r"(b[1]));
}

template<int BM, int BN, int BK, int WM, int WN, bool TRANSB>
__global__ void __launch_bounds__((BM / WM) * (BN / WN) * 32)
tf32x3gemm_kernel(
    int M, int Nc, int K,
    const float* __restrict__ A, int lda, long sA,
    const float* __restrict__ B, int ldb, long sB,
    float* __restrict__ Cout, long sC,
    const float* __restrict__ alphaVec,
    float beta, int mode, int p1, int p2, int p3)
{
    constexpr int NWARP = (BM / WM) * (BN / WN);
    constexpr int NTH   = NWARP * 32;
    constexpr int LDA_S = BK + 4;
    constexpr int LDB_S = BN + 4;
    constexpr int MFR = WM / 16;
    constexpr int NFR = WN / 8;

    __shared__ uint32_t AsH[BM * LDA_S];
    __shared__ uint32_t AsL[BM * LDA_S];
    __shared__ uint32_t BsH[BK * LDB_S];
    __shared__ uint32_t BsL[BK * LDB_S];

    const int z = blockIdx.z;
    const float* Ab = A + (long)z * sA;
    const float* Bb = B + (long)z * sB;

    const int tid  = threadIdx.x;
    const int warp = tid >> 5;
    const int lane = tid & 31;
    const int g    = lane >> 2;
    const int tg   = lane & 3;
    const int wr   = warp / (BN / WN);
    const int wc   = warp % (BN / WN);
    const int rowBase = blockIdx.y * BM;
    const int colBase = blockIdx.x * BN;

    float acc[MFR][NFR][4];
    #pragma unroll
    for (int i = 0; i < MFR; i++)
        #pragma unroll
        for (int j = 0; j < NFR; j++)
            #pragma unroll
            for (int q = 0; q < 4; q++) acc[i][j][q] = 0.0f;

    for (int k0 = 0; k0 < K; k0 += BK) {
        #pragma unroll
        for (int idx = tid; idx < BM * (BK / 4); idx += NTH) {
            int r  = idx / (BK / 4);
            int k4 = (idx % (BK / 4)) * 4;
            int gr = rowBase + r;
            float4 v = make_float4(0.f, 0.f, 0.f, 0.f);
            if (gr < M && (k0 + k4) < K)
                v = *reinterpret_cast<const float4*>(&Ab[(long)gr * lda + k0 + k4]);
            uint32_t* dh = &AsH[r * LDA_S + k4];
            uint32_t* dl = &AsL[r * LDA_S + k4];
            split_tf32(v.x, dh[0], dl[0]); split_tf32(v.y, dh[1], dl[1]);
            split_tf32(v.z, dh[2], dl[2]); split_tf32(v.w, dh[3], dl[3]);
        }
        if (!TRANSB) {
            #pragma unroll
            for (int idx = tid; idx < BK * (BN / 4); idx += NTH) {
                int r  = idx / (BN / 4);
                int c4 = (idx % (BN / 4)) * 4;
                int gc = colBase + c4;
                float4 v = make_float4(0.f, 0.f, 0.f, 0.f);
                if ((k0 + r) < K && gc < Nc)
                    v = *reinterpret_cast<const float4*>(&Bb[(long)(k0 + r) * ldb + gc]);
                uint32_t* dh = &BsH[r * LDB_S + c4];
                uint32_t* dl = &BsL[r * LDB_S + c4];
                split_tf32(v.x, dh[0], dl[0]); split_tf32(v.y, dh[1], dl[1]);
                split_tf32(v.z, dh[2], dl[2]); split_tf32(v.w, dh[3], dl[3]);
            }
        } else {
            #pragma unroll
            for (int idx = tid; idx < BN * (BK / 4); idx += NTH) {
                int c  = idx / (BK / 4);
                int k4 = (idx % (BK / 4)) * 4;
                int gc = colBase + c;
                float4 v = make_float4(0.f, 0.f, 0.f, 0.f);
                if (gc < Nc && (k0 + k4) < K)
                    v = *reinterpret_cast<const float4*>(&Bb[(long)gc * ldb + k0 + k4]);
                split_tf32(v.x, BsH[(k4 + 0) * LDB_S + c], BsL[(k4 + 0) * LDB_S + c]);
                split_tf32(v.y, BsH[(k4 + 1) * LDB_S + c], BsL[(k4 + 1) * LDB_S + c]);
                split_tf32(v.z, BsH[(k4 + 2) * LDB_S + c], BsL[(k4 + 2) * LDB_S + c]);
                split_tf32(v.w, BsH[(k4 + 3) * LDB_S + c], BsL[(k4 + 3) * LDB_S + c]);
            }
        }
        __syncthreads();

        #pragma unroll
        for (int kk = 0; kk < BK; kk += 8) {
            uint32_t afH[MFR][4], afL[MFR][4];
            uint32_t bfH[NFR][2], bfL[NFR][2];
            #pragma unroll
            for (int mi = 0; mi < MFR; mi++) {
                int mrow = wr * WM + mi * 16 + g;
                int i00 = (mrow    ) * LDA_S + kk + tg;
                int i10 = (mrow + 8) * LDA_S + kk + tg;
                afH[mi][0] = AsH[i00];     afL[mi][0] = AsL[i00];
                afH[mi][1] = AsH[i10];     afL[mi][1] = AsL[i10];
                afH[mi][2] = AsH[i00 + 4]; afL[mi][2] = AsL[i00 + 4];
                afH[mi][3] = AsH[i10 + 4]; afL[mi][3] = AsL[i10 + 4];
            }
            #pragma unroll
            for (int ni = 0; ni < NFR; ni++) {
                int ncol = wc * WN + ni * 8 + g;
                int j0 = (kk + tg    ) * LDB_S + ncol;
                int j1 = (kk + tg + 4) * LDB_S + ncol;
                bfH[ni][0] = BsH[j0]; bfL[ni][0] = BsL[j0];
                bfH[ni][1] = BsH[j1]; bfL[ni][1] = BsL[j1];
            }
            #pragma unroll
            for (int mi = 0; mi < MFR; mi++)
                #pragma unroll
                for (int ni = 0; ni < NFR; ni++) {
                    float* c = acc[mi][ni];
                    mma_tf32(c, afL[mi], bfH[ni]);   // lo*hi
                    mma_tf32(c, afH[mi], bfL[ni]);   // hi*lo
                    mma_tf32(c, afH[mi], bfH[ni]);   // hi*hi
                }
        }
        __syncthreads();
    }

    float alpha = 1.0f;
    if (alphaVec) alpha = alphaVec[z % HH];

    #pragma unroll
    for (int mi = 0; mi < MFR; mi++) {
        #pragma unroll
        for (int half = 0; half < 2; half++) {
            int gr = rowBase + wr * WM + mi * 16 + g + half * 8;
            if (gr >= M) continue;
            #pragma unroll
            for (int ni = 0; ni < NFR; ni++) {
                #pragma unroll
                for (int e = 0; e < 2; e++) {
                    int gc = colBase + wc * WN + ni * 8 + tg * 2 + e;
                    if (gc >= Nc) continue;
                    float val = alpha * acc[mi][ni][half * 2 + e];
                    if (mode == 0) {
                        float* cp = Cout + (long)gr * p1 + gc;
                        *cp = (beta == 0.0f) ? val : fmaf(beta, *cp, val);
                    } else if (mode == 1) {
                        int b = gr / p1;
                        int rr = gr - b * p1;
                        int h = gc >> 6, d = gc & 63;
                        Cout[(((long)(b * HH + h) * p2 + p3 + rr) << 6) + d] = val;
                    } else if (mode == 2) {
                        int b = z >> 4, h = z & 15;
                        Cout[(((long)(b * p1 + gr) * HH + h) << 6) + gc] = val;
                    } else {
                        Cout[(long)z * sC + (long)gr * p1 + gc] = val;
                    }
                }
            }
        }
    }
}

// ---------------- host launch ------------------------------------------------

static constexpr size_t MIX_SMEM = (size_t)HH * JJ * sizeof(float); // 132096

extern "C" void kernel_launch(void* const* d_in, const int* in_sizes, int n_in,
                              void* d_out, int out_size)
{
    (void)in_sizes; (void)n_in; (void)out_size;
    const float* x   = (const float*)d_in[0];
    const float* ctx = (const float*)d_in[1];
    const float* wq[2]     = {(const float*)d_in[2],  (const float*)d_in[5]};
    const float* wk[2]     = {(const float*)d_in[3],  (const float*)d_in[6]};
    const float* wv[2]     = {(const float*)d_in[4],  (const float*)d_in[7]};
    const float* thpre[2]  = {(const float*)d_in[8],  (const float*)d_in[10]};
    const float* thpost[2] = {(const float*)d_in[9],  (const float*)d_in[11]};
    const float* scp[2]    = {(const float*)d_in[12], (const float*)d_in[13]};
    const float* mk[2]     = {(const float*)d_in[14], (const float*)d_in[16]};
    const float* mv[2]     = {(const float*)d_in[15], (const float*)d_in[17]};
    const float* hs[2]     = {(const float*)d_in[18], (const float*)d_in[19]};
    const float* wo[2]     = {(const float*)d_in[20], (const float*)d_in[21]};
    float* out = (float*)d_out;

    float *qn, *kn, *vv, *dots, *cat, *scl;
    cudaGetSymbolAddress((void**)&qn,   g_qn);
    cudaGetSymbolAddress((void**)&kn,   g_kn);
    cudaGetSymbolAddress((void**)&vv,   g_vv);
    cudaGetSymbolAddress((void**)&dots, g_dots);
    cudaGetSymbolAddress((void**)&cat,  g_cat);
    cudaGetSymbolAddress((void**)&scl,  g_scale);

    cudaFuncSetAttribute(mix_softmax_kernel,
                         cudaFuncAttributeMaxDynamicSharedMemorySize, (int)MIX_SMEM);

    for (int l = 0; l < 2; l++) {
        scale_kernel<<<1, 16>>>(scl, scp[l]);

        // Q = x @ wq  -> qn [b][h][n][d]
        tf32x3gemm_kernel<128, 128, 16, 64, 32, false><<<dim3(8, 16, 1), 256>>>(
            Bc * Nq, DIM, DIM, x, DIM, 0, wq[l], DIM, 0, qn, 0,
            nullptr, 0.0f, 1, Nq, Nq, 0);

        const float* c = ctx + (size_t)l * Bc * NCTX * DIM;
        // K = ctx @ wk -> kn rows [NMEM..J)
        tf32x3gemm_kernel<128, 128, 16, 64, 32, false><<<dim3(8, 32, 1), 256>>>(
            Bc * NCTX, DIM, DIM, c, DIM, 0, wk[l], DIM, 0, kn, 0,
            nullptr, 0.0f, 1, NCTX, JJ, NMEM);
        // V = ctx @ wv -> vv rows [NMEM..J)
        tf32x3gemm_kernel<128, 128, 16, 64, 32, false><<<dim3(8, 32, 1), 256>>>(
            Bc * NCTX, DIM, DIM, c, DIM, 0, wv[l], DIM, 0, vv, 0,
            nullptr, 0.0f, 1, NCTX, JJ, NMEM);

        memfill_kernel<<<64, 256>>>(kn, vv, mk[l], mv[l]);

        l2norm_kernel<<<(Bc * HH * Nq + 7) / 8, 256>>>(qn, Bc * HH * Nq);
        l2norm_kernel<<<(Bc * HH * JJ + 7) / 8, 256>>>(kn, Bc * HH * JJ);

        // dots = scale[h] * qn @ kn^T   (batched over z = b*16+h)
        tf32x3gemm_kernel<128, 128, 16, 64, 32, true><<<dim3(17, 8, 32), 256>>>(
            Nq, JJ, DHH, qn, DHH, (long)Nq * DHH, kn, DHH, (long)JJ * DHH,
            dots, (long)Nq * JJ, scl, 0.0f, 3, JJ, 0, 0);

        // talking-heads pre-mix + softmax + post-mix (in place)
        mix_softmax_kernel<<<Bc * Nq, 256, MIX_SMEM>>>(dots, thpre[l], thpost[l]);

        // out_heads = hs[h] * attn @ v -> cat [b][n][h][d]
        tf32x3gemm_kernel<128, 64, 16, 64, 32, false><<<dim3(1, 8, 32), 128>>>(
            Nq, DHH, JJ, dots, JJ, (long)Nq * JJ, vv, DHH, (long)JJ * DHH,
            cat, 0, hs[l], 0.0f, 2, Nq, 0, 0);

        // out (+)= cat @ wo
        tf32x3gemm_kernel<128, 128, 16, 64, 32, false><<<dim3(8, 16, 1), 256>>>(
            Bc * Nq, DIM, DIM, cat, DIM, 0, wo[l], DIM, 0, out, 0,
            nullptr, (l == 0 ? 0.0f : 1.0f), 0, DIM, 0, 0);
    }
}